// round 8
// baseline (speedup 1.0000x reference)
#include <cuda_runtime.h>
#include <math.h>

#define NXD 32
#define HID 256
#define NOUT 528
#define BM 32
#define NTHREADS 512
#define HSTR 36
#define LSTRIDE 532

// shared layout (float offsets), total 26240 floats = 104960 B -> 2 blocks/SM
#define OFF_H2 0        // 256*36 = 9216
#define OFF_X  9216     // 32*36  = 1152  (dead after G1)
#define OFF_H1 10368    // 256*36 = 9216  (dead after G2)
#define OFF_L  9216     // 32*532 = 17024 (overlays X+H1)
#define SMEM_FLOATS 26240

typedef unsigned long long u64;

__device__ __forceinline__ u64 pk2(float lo, float hi) {
    u64 d; asm("mov.b64 %0, {%1, %2};" : "=l"(d) : "f"(lo), "f"(hi)); return d;
}
__device__ __forceinline__ void fma2(u64& d, u64 a, u64 b) {
    asm("fma.rn.f32x2 %0, %1, %2, %0;" : "+l"(d) : "l"(a), "l"(b));
}
__device__ __forceinline__ float2 up2(u64 d) {
    float2 r; asm("mov.b64 {%0, %1}, %2;" : "=f"(r.x), "=f"(r.y) : "l"(d)); return r;
}
__device__ __forceinline__ u64 swp2(u64 d) {
    float2 r = up2(d); return pk2(r.y, r.x);
}
__device__ __forceinline__ float ftanh(float x) {
    x = fminf(fmaxf(x, -15.f), 15.f);
    float e = __expf(2.f * x);
    return __fdividef(e - 1.f, e + 1.f);
}
__device__ __forceinline__ float fsplus(float v) {
    float sp = (v > 20.f) ? v : __logf(1.f + __expf(v));
    return fminf(fmaxf(sp + 0.01f, 0.01f), 100.f);
}

// Warp tile: 32 samples x 16 cols (warp wp owns cols 16wp..16wp+15).
// Lane: r=tx&7 -> samples sbase=4r..4r+3 ; c=tx>>3 -> cols cbase=16wp+4c..+3.
// W operand: direct LDG.128 from global (no smem staging, no mainloop barriers).
// Mixed f32x2 packing (as R7):
//   accP[sp][j] = (P[sa][c0], P[sb][c1]),  accQ[sp][j] = (P[sa][c1], P[sb][c0])
// MODE 0: tanh -> transposed outp[col*HSTR + s]
// MODE 1: GEMM3 cols [0,256): wp<2 -> softplus else 0.1*tanh -> sL[s*LSTRIDE + col]
// MODE 2: GEMM3 cols [256,512) + tail col 512+wp via accS -> sL
template<int KTOT, int MODE>
__device__ __forceinline__ void gemm_direct(
    const float* __restrict__ Wg, int ldw,
    const float* __restrict__ bias,
    const float* sHin, float* outp,
    int sbase, int cbase, int wp, int tx)
{
    u64 accP[2][2], accQ[2][2];
    {
        float4 b4 = *(const float4*)&bias[cbase];
        u64 bp0 = pk2(b4.x, b4.y), bq0 = pk2(b4.y, b4.x);
        u64 bp1 = pk2(b4.z, b4.w), bq1 = pk2(b4.w, b4.z);
        accP[0][0] = bp0; accP[1][0] = bp0; accQ[0][0] = bq0; accQ[1][0] = bq0;
        accP[0][1] = bp1; accP[1][1] = bp1; accQ[0][1] = bq1; accQ[1][1] = bq1;
    }
    u64 accS[2];
    if (MODE == 2) {
        float bs = __ldg(&bias[256 + wp]);
        accS[0] = pk2(bs, bs); accS[1] = accS[0];
    }

    const int KQ = KTOT / 4;
    #pragma unroll 2
    for (int q = 0; q < KQ; q++) {
        ulonglong2 w4[4];
        float ws4[4];
        #pragma unroll
        for (int m = 0; m < 4; m++) {
            w4[m] = *(const ulonglong2*)&Wg[(size_t)(4 * q + m) * ldw + cbase];
            if (MODE == 2)
                ws4[m] = __ldg(&Wg[(size_t)(4 * q + m) * ldw + 256 + wp]);
        }
        #pragma unroll
        for (int m = 0; m < 4; m++) {
            ulonglong2 hv = *(const ulonglong2*)&sHin[(4 * q + m) * HSTR + sbase];
            u64 wx = w4[m].x, wy = w4[m].y;
            u64 wxs = swp2(wx), wys = swp2(wy);
            fma2(accP[0][0], hv.x, wx); fma2(accQ[0][0], hv.x, wxs);
            fma2(accP[0][1], hv.x, wy); fma2(accQ[0][1], hv.x, wys);
            fma2(accP[1][0], hv.y, wx); fma2(accQ[1][0], hv.y, wxs);
            fma2(accP[1][1], hv.y, wy); fma2(accQ[1][1], hv.y, wys);
            if (MODE == 2) {
                u64 wsd = pk2(ws4[m], ws4[m]);
                fma2(accS[0], hv.x, wsd);
                fma2(accS[1], hv.y, wsd);
            }
        }
    }

    // epilogue
    if (MODE == 0) {
        #pragma unroll
        for (int j = 0; j < 2; j++) {
            float2 P0 = up2(accP[0][j]), Q0 = up2(accQ[0][j]);
            float2 P1 = up2(accP[1][j]), Q1 = up2(accQ[1][j]);
            int c0 = cbase + 2 * j;
            float4 v0 = { ftanh(P0.x), ftanh(Q0.y), ftanh(P1.x), ftanh(Q1.y) };
            float4 v1 = { ftanh(Q0.x), ftanh(P0.y), ftanh(Q1.x), ftanh(P1.y) };
            *(float4*)&outp[c0 * HSTR + sbase]       = v0;
            *(float4*)&outp[(c0 + 1) * HSTR + sbase] = v1;
        }
    } else {
        #pragma unroll
        for (int sp = 0; sp < 2; sp++) {
            float2 p0 = up2(accP[sp][0]), q0 = up2(accQ[sp][0]);
            float2 p1 = up2(accP[sp][1]), q1 = up2(accQ[sp][1]);
            float ea[4] = { p0.x, q0.x, p1.x, q1.x };
            float eb[4] = { q0.y, p0.y, q1.y, p1.y };
            float oa[4], ob[4];
            bool dg = (MODE == 1) && (wp < 2);   // warp-uniform diag path
            #pragma unroll
            for (int m = 0; m < 4; m++) {
                oa[m] = dg ? fsplus(ea[m]) : 0.1f * ftanh(ea[m]);
                ob[m] = dg ? fsplus(eb[m]) : 0.1f * ftanh(eb[m]);
            }
            const int off = (MODE == 2) ? 256 : 0;
            int sa = sbase + 2 * sp;
            *(float4*)&outp[sa * LSTRIDE + off + cbase]       = *(float4*)oa;
            *(float4*)&outp[(sa + 1) * LSTRIDE + off + cbase] = *(float4*)ob;
        }
        if (MODE == 2 && tx < 8) {
            float2 s0 = up2(accS[0]), s1 = up2(accS[1]);
            outp[(sbase + 0) * LSTRIDE + 512 + wp] = 0.1f * ftanh(s0.x);
            outp[(sbase + 1) * LSTRIDE + 512 + wp] = 0.1f * ftanh(s0.y);
            outp[(sbase + 2) * LSTRIDE + 512 + wp] = 0.1f * ftanh(s1.x);
            outp[(sbase + 3) * LSTRIDE + 512 + wp] = 0.1f * ftanh(s1.y);
        }
    }
}

__global__ void __launch_bounds__(NTHREADS, 2) covnet_kernel(
    const float* __restrict__ P_prev,
    const float* __restrict__ W1, const float* __restrict__ b1,
    const float* __restrict__ W2, const float* __restrict__ b2,
    const float* __restrict__ W3, const float* __restrict__ b3,
    const float* __restrict__ Q, float* __restrict__ out)
{
    extern __shared__ float sm[];
    const int tid = threadIdx.x;
    const int tx = tid & 31;
    const int wp = tid >> 5;
    const int sbase = 4 * (tx & 7);
    const int cbase = 16 * wp + 4 * (tx >> 3);
    const size_t b0 = (size_t)blockIdx.x * BM;

    // gather diagonal (transposed): sXt[d*HSTR + s] = log(clip(P_prev[s,d,d]))
    for (int i = tid; i < NXD * BM; i += NTHREADS) {
        int d = i >> 5, s = i & 31;
        float v = P_prev[(b0 + (size_t)s) * 1024 + d * 33];
        sm[OFF_X + d * HSTR + s] = __logf(fmaxf(v, 1e-6f));
    }
    __syncthreads();

    gemm_direct<32,  0>(W1,       HID,  b1,       sm + OFF_X,  sm + OFF_H1, sbase, cbase, wp, tx);
    __syncthreads();
    gemm_direct<256, 0>(W2,       HID,  b2,       sm + OFF_H1, sm + OFF_H2, sbase, cbase, wp, tx);
    __syncthreads();
    gemm_direct<256, 1>(W3,       NOUT, b3,       sm + OFF_H2, sm + OFF_L,  sbase, cbase, wp, tx);
    gemm_direct<256, 2>(W3 + 256, NOUT, b3 + 256, sm + OFF_H2, sm + OFF_L,  sbase, cbase, wp, tx);
    __syncthreads();

    // ================= P = L * L^T + Q =================
    // warp handles 2 samples. Lane k holds row k of L in registers (zero-padded);
    // capture via aligned broadcast loads + predicated select; compute via shfl.
    {
        const int k = tx;
        for (int ss = 0; ss < 2; ss++) {
            const int s = 2 * wp + ss;
            const float* Lr = sm + OFF_L + s * LSTRIDE;

            float Lk[32];
            #pragma unroll
            for (int j = 0; j < 32; j++) Lk[j] = 0.f;

            // capture diagonal: Lk[k] = Lr[k]
            #pragma unroll
            for (int qd = 0; qd < 8; qd++) {
                float4 d4 = *(const float4*)&Lr[4 * qd];
                if (k == 4 * qd + 0) Lk[4 * qd + 0] = d4.x;
                if (k == 4 * qd + 1) Lk[4 * qd + 1] = d4.y;
                if (k == 4 * qd + 2) Lk[4 * qd + 2] = d4.z;
                if (k == 4 * qd + 3) Lk[4 * qd + 3] = d4.w;
            }

            // capture lower rows: lane i captures row i (i entries at ib)
            #pragma unroll
            for (int i = 1; i < 32; i++) {
                const int ib = 32 + i * (i - 1) / 2;
                const bool mine = (k == i);
                int j = 0;
                if (ib & 1) {                       // compile-time per i
                    float v = Lr[ib];
                    if (mine) Lk[0] = v;
                    j = 1;
                }
                #pragma unroll
                for (; j + 1 < i; j += 2) {
                    float2 v = *(const float2*)&Lr[ib + j];
                    if (mine) { Lk[j] = v.x; Lk[j + 1] = v.y; }
                }
                if (j < i) {
                    float v = Lr[ib + j];
                    if (mine) Lk[j] = v;
                }
            }

            // compute: P[i][k] = Q[i][k] + sum_j row_i[j] * row_k[j]
            float* Po = out + (b0 + (size_t)s) * 1024;
            #pragma unroll
            for (int i = 0; i < 32; i++) {
                float a = __ldg(&Q[i * 32 + k]);
                #pragma unroll
                for (int j = 0; j <= i; j++)
                    a += __shfl_sync(0xffffffffu, Lk[j], i) * Lk[j];
                Po[i * 32 + k] = a;
            }
        }
    }
}

extern "C" void kernel_launch(void* const* d_in, const int* in_sizes, int n_in,
                              void* d_out, int out_size) {
    const float* P_prev = (const float*)d_in[0];
    const float* W1 = (const float*)d_in[1];
    const float* b1 = (const float*)d_in[2];
    const float* W2 = (const float*)d_in[3];
    const float* b2 = (const float*)d_in[4];
    const float* W3 = (const float*)d_in[5];
    const float* b3 = (const float*)d_in[6];
    const float* Q  = (const float*)d_in[7];
    float* out = (float*)d_out;

    const int B = in_sizes[0] / (NXD * NXD);   // 65536
    const int grid = B / BM;                   // 2048

    cudaFuncSetAttribute(covnet_kernel,
                         cudaFuncAttributeMaxDynamicSharedMemorySize,
                         SMEM_FLOATS * sizeof(float));

    covnet_kernel<<<grid, NTHREADS, SMEM_FLOATS * sizeof(float)>>>(
        P_prev, W1, b1, W2, b2, W3, b3, Q, out);
}

// round 9
// speedup vs baseline: 1.1535x; 1.1535x over previous
#include <cuda_runtime.h>
#include <math.h>

#define NXD 32
#define HID 256
#define NOUT 528
#define BM 64
#define NTHREADS 256
#define HSTR 68
#define WSTR 272
#define LSTRIDE 533

// shared layout (float offsets), total 55872 floats = 223488 B, 1 block/SM
#define OFF_H2 0        // 256*68 = 17408
#define OFF_W0 17408    // 8*272 = 2176
#define OFF_W1 19584    // 8*272 = 2176
#define OFF_X  21760    // 32*68 = 2176   (dead after G1)
#define OFF_H1 23936    // 256*68 = 17408 (dead after G2)
#define OFF_L  21760    // 64*533 = 34112 (overlays X+H1)
#define SMEM_FLOATS 55872

typedef unsigned long long u64;

__device__ __forceinline__ u64 pk2(float lo, float hi) {
    u64 d; asm("mov.b64 %0, {%1, %2};" : "=l"(d) : "f"(lo), "f"(hi)); return d;
}
__device__ __forceinline__ void fma2(u64& d, u64 a, u64 b) {
    asm("fma.rn.f32x2 %0, %1, %2, %0;" : "+l"(d) : "l"(a), "l"(b));
}
__device__ __forceinline__ float2 up2(u64 d) {
    float2 r; asm("mov.b64 {%0, %1}, %2;" : "=f"(r.x), "=f"(r.y) : "l"(d)); return r;
}
__device__ __forceinline__ float ftanh(float x) {
    x = fminf(fmaxf(x, -15.f), 15.f);
    float e = __expf(2.f * x);
    return __fdividef(e - 1.f, e + 1.f);
}
__device__ __forceinline__ float fsplus(float v) {
    float sp = (v > 20.f) ? v : __logf(1.f + __expf(v));
    return fminf(fmaxf(sp + 0.01f, 0.01f), 100.f);
}

// Block 64s x 256c. Warp (wr=wp&1, wc=wp>>1): 32s x 64c.
// Lane: r=tx>>3 -> samples sbase=32wr+8r..+7 ; c=tx&7 -> cols 64wc+c+8t, t=0..7
// (interleaved col ownership -> conflict-free scalar w-loads and L-stores).
// acc[sp][t] = f32x2 over sample pair (sbase+2sp, sbase+2sp+1), col 64wc+c+8t.
// MODE 0: tanh -> transposed outp[col*HSTR + s]   (h1/h2)
// MODE 1: G3 cols [0,256): diag(global col<32) softplus else 0.1*tanh -> sL
// MODE 2: G3 cols [256,512) + tail cols 512+4wc+q (q=0..3) via accS -> sL
template<int KTOT, int MODE>
__device__ __forceinline__ void gemm_tile(
    float* sm, const float* __restrict__ Wg, int ldw,
    const float* __restrict__ bias,
    const float* sHin, float* outp,
    int sbase, int cbase, int wc, int tx)
{
    const int NCH = KTOT / 8;
    const int NOFF = (MODE == 2) ? 256 : 0;

    u64 acc[4][8];
    #pragma unroll
    for (int t = 0; t < 8; t++) {
        float bv = __ldg(&bias[cbase + 8 * t]);
        u64 bd = pk2(bv, bv);
        #pragma unroll
        for (int sp = 0; sp < 4; sp++) acc[sp][t] = bd;
    }
    u64 accS[4][4];
    if (MODE == 2) {
        #pragma unroll
        for (int q = 0; q < 4; q++) {
            float bv = __ldg(&bias[256 + 4 * wc + q]);
            u64 bd = pk2(bv, bv);
            #pragma unroll
            for (int sp = 0; sp < 4; sp++) accS[q][sp] = bd;
        }
    }

    float* buf0 = sm + OFF_W0;
    float* buf1 = sm + OFF_W1;
    float4 rgA, rgB, rgT;

    auto stage_ld = [&](int ch) {
        int row = threadIdx.x >> 5, c4 = threadIdx.x & 31;
        const float* src = Wg + (size_t)(ch * 8 + row) * ldw;
        rgA = *(const float4*)(src + 4 * c4);
        rgB = *(const float4*)(src + 4 * c4 + 128);
        if (MODE == 2 && threadIdx.x < 32) {
            int row2 = threadIdx.x >> 2, c2 = threadIdx.x & 3;
            rgT = *(const float4*)(Wg + (size_t)(ch * 8 + row2) * ldw + 256 + 4 * c2);
        }
    };
    auto stage_st = [&](float* buf) {
        int row = threadIdx.x >> 5, c4 = threadIdx.x & 31;
        *(float4*)(buf + row * WSTR + 4 * c4) = rgA;
        *(float4*)(buf + row * WSTR + 4 * c4 + 128) = rgB;
        if (MODE == 2 && threadIdx.x < 32) {
            int row2 = threadIdx.x >> 2, c2 = threadIdx.x & 3;
            *(float4*)(buf + row2 * WSTR + 256 + 4 * c2) = rgT;
        }
    };

    stage_ld(0);
    stage_st(buf0);
    __syncthreads();

    for (int ch = 0; ch < NCH; ch++) {
        float* cur = (ch & 1) ? buf1 : buf0;
        float* nxt = (ch & 1) ? buf0 : buf1;
        if (ch + 1 < NCH) stage_ld(ch + 1);
        const int kc = ch * 8;
        #pragma unroll
        for (int kk = 0; kk < 8; kk++) {
            const float* hrow = sHin + (kc + kk) * HSTR + sbase;
            ulonglong2 hA = *(const ulonglong2*)hrow;
            ulonglong2 hB = *(const ulonglong2*)(hrow + 4);
            u64 hd0 = hA.x, hd1 = hA.y, hd2 = hB.x, hd3 = hB.y;
            const float* wrow = cur + kk * WSTR;
            #pragma unroll
            for (int t = 0; t < 8; t++) {
                float wv = wrow[cbase + 8 * t];
                u64 wd = pk2(wv, wv);
                fma2(acc[0][t], hd0, wd);
                fma2(acc[1][t], hd1, wd);
                fma2(acc[2][t], hd2, wd);
                fma2(acc[3][t], hd3, wd);
            }
            if (MODE == 2) {
                #pragma unroll
                for (int q = 0; q < 4; q++) {
                    float wv = wrow[256 + 4 * wc + q];
                    u64 wd = pk2(wv, wv);
                    fma2(accS[q][0], hd0, wd);
                    fma2(accS[q][1], hd1, wd);
                    fma2(accS[q][2], hd2, wd);
                    fma2(accS[q][3], hd3, wd);
                }
            }
        }
        if (ch + 1 < NCH) stage_st(nxt);
        __syncthreads();
    }

    // epilogue
    if (MODE == 0) {
        #pragma unroll
        for (int t = 0; t < 8; t++) {
            int col = cbase + 8 * t;
            #pragma unroll
            for (int sp = 0; sp < 4; sp++) {
                float2 v = up2(acc[sp][t]);
                float2 o = { ftanh(v.x), ftanh(v.y) };
                *(float2*)&outp[col * HSTR + sbase + 2 * sp] = o;
            }
        }
    } else {
        #pragma unroll
        for (int sp = 0; sp < 4; sp++) {
            #pragma unroll
            for (int e = 0; e < 2; e++) {
                const int s = sbase + 2 * sp + e;
                float* Ls = outp + s * LSTRIDE + NOFF;
                #pragma unroll
                for (int t = 0; t < 8; t++) {
                    float2 v = up2(acc[sp][t]);
                    float val = e ? v.y : v.x;
                    bool dg = (MODE == 1) && (wc == 0) && (t < 4);  // global col < 32
                    Ls[cbase + 8 * t] = dg ? fsplus(val) : 0.1f * ftanh(val);
                }
            }
        }
        if (MODE == 2 && (tx & 7) == 0) {   // c==0 lanes hold valid accS
            #pragma unroll
            for (int q = 0; q < 4; q++) {
                const int col = 512 + 4 * wc + q;
                #pragma unroll
                for (int sp = 0; sp < 4; sp++) {
                    float2 v = up2(accS[q][sp]);
                    int s = sbase + 2 * sp;
                    outp[s * LSTRIDE + col]       = 0.1f * ftanh(v.x);
                    outp[(s + 1) * LSTRIDE + col] = 0.1f * ftanh(v.y);
                }
            }
        }
    }
}

__global__ void __launch_bounds__(NTHREADS, 1) covnet_kernel(
    const float* __restrict__ P_prev,
    const float* __restrict__ W1, const float* __restrict__ b1,
    const float* __restrict__ W2, const float* __restrict__ b2,
    const float* __restrict__ W3, const float* __restrict__ b3,
    const float* __restrict__ Q, float* __restrict__ out)
{
    extern __shared__ float sm[];
    const int tid = threadIdx.x;
    const int tx = tid & 31;
    const int wp = tid >> 5;            // 0..7
    const int wr = wp & 1, wc = wp >> 1;
    const int sbase = 32 * wr + 8 * (tx >> 3);
    const int cbase = 64 * wc + (tx & 7);
    const size_t b0 = (size_t)blockIdx.x * BM;

    // gather diagonal (transposed): sX[d*HSTR + s] = log(clip(P_prev[s,d,d]))
    for (int i = tid; i < NXD * BM; i += NTHREADS) {
        int d = i >> 6, s = i & 63;
        float v = P_prev[(b0 + (size_t)s) * 1024 + d * 33];
        sm[OFF_X + d * HSTR + s] = __logf(fmaxf(v, 1e-6f));
    }
    __syncthreads();

    gemm_tile<32,  0>(sm, W1,       HID,  b1,       sm + OFF_X,  sm + OFF_H1, sbase, cbase, wc, tx);
    gemm_tile<256, 0>(sm, W2,       HID,  b2,       sm + OFF_H1, sm + OFF_H2, sbase, cbase, wc, tx);
    gemm_tile<256, 1>(sm, W3,       NOUT, b3,       sm + OFF_H2, sm + OFF_L,  sbase, cbase, wc, tx);
    gemm_tile<256, 2>(sm, W3 + 256, NOUT, b3 + 256, sm + OFF_H2, sm + OFF_L,  sbase, cbase, wc, tx);
    __syncthreads();

    // ================= P = L * L^T + Q =================
    // warp wp handles samples 8wp..8wp+7; lane k owns output column k.
    // Q column k cached in registers; row k gathered per sample; rows via shfl.
    {
        const int k = tx;
        float Qk[32];
        #pragma unroll
        for (int i = 0; i < 32; i++) Qk[i] = __ldg(&Q[i * 32 + k]);
        const int kb = 32 + k * (k - 1) / 2;

        #pragma unroll 1
        for (int ss = 0; ss < 8; ss++) {
            const int s = 8 * wp + ss;
            const float* Lr = sm + OFF_L + s * LSTRIDE;

            float Lk[32];
            #pragma unroll
            for (int j = 0; j < 32; j++) {
                float tv = 0.f;
                int addr = (j < k) ? (kb + j) : j;   // lower part or diagonal
                if (j <= k) tv = Lr[addr];
                Lk[j] = tv;
            }

            float* Po = out + (b0 + (size_t)s) * 1024;
            #pragma unroll
            for (int i = 0; i < 32; i++) {
                float a = Qk[i];
                #pragma unroll
                for (int j = 0; j <= i; j++)
                    a += __shfl_sync(0xffffffffu, Lk[j], i) * Lk[j];
                Po[i * 32 + k] = a;
            }
        }
    }
}

extern "C" void kernel_launch(void* const* d_in, const int* in_sizes, int n_in,
                              void* d_out, int out_size) {
    const float* P_prev = (const float*)d_in[0];
    const float* W1 = (const float*)d_in[1];
    const float* b1 = (const float*)d_in[2];
    const float* W2 = (const float*)d_in[3];
    const float* b2 = (const float*)d_in[4];
    const float* W3 = (const float*)d_in[5];
    const float* b3 = (const float*)d_in[6];
    const float* Q  = (const float*)d_in[7];
    float* out = (float*)d_out;

    const int B = in_sizes[0] / (NXD * NXD);   // 65536
    const int grid = B / BM;                   // 1024

    cudaFuncSetAttribute(covnet_kernel,
                         cudaFuncAttributeMaxDynamicSharedMemorySize,
                         SMEM_FLOATS * sizeof(float));

    covnet_kernel<<<grid, NTHREADS, SMEM_FLOATS * sizeof(float)>>>(
        P_prev, W1, b1, W2, b2, W3, b3, Q, out);
}